// round 15
// baseline (speedup 1.0000x reference)
#include <cuda_runtime.h>
#include <cuda_bf16.h>
#include <cstdint>

#define NN   50000
#define EE   800000
#define HIDD 128
#define MLP0 512
#define MLP1 256

// weight arena offsets (elements)
#define WOFF_G0 0
#define WOFF_G1 16384
#define WOFF_G2 32768
#define WOFF_M0 49152
#define WOFF_M1 114688
#define WTOTAL  245760

// ---------------- scratch (device globals; device-code-only references) ----------------
__device__ float         g_H[(size_t)NN * HIDD];
__device__ __nv_bfloat16 g_Ahi[(size_t)NN * HIDD];
__device__ __nv_bfloat16 g_Alo[(size_t)NN * HIDD];
__device__ __nv_bfloat16 g_Bhi[(size_t)NN * MLP0];
__device__ __nv_bfloat16 g_Blo[(size_t)NN * MLP0];
__device__ __nv_bfloat16 g_Wshi[WTOTAL];
__device__ __nv_bfloat16 g_Wslo[WTOTAL];
__device__ int   g_cnt[NN + 1];
__device__ int   g_rowptr[NN + 1];
__device__ int   g_fill[NN];
__device__ float g_dinv[NN];
__device__ int   g_csr_src[EE];
__device__ float g_csr_w[EE];
__device__ int   g_is64;
__device__ int   g_bsum[256];
__device__ int   g_boff[256];

#define SCAN_B 256
#define SCAN_NB ((NN + SCAN_B - 1) / SCAN_B)   // 196

// ---------------- helpers ----------------
__device__ __forceinline__ void split_pack(float x, float y, uint32_t& hi, uint32_t& lo) {
    __nv_bfloat16 hx = __float2bfloat16_rn(x);
    __nv_bfloat16 hy = __float2bfloat16_rn(y);
    float rx = x - __bfloat162float(hx);
    float ry = y - __bfloat162float(hy);
    __nv_bfloat16 lx = __float2bfloat16_rn(rx);
    __nv_bfloat16 ly = __float2bfloat16_rn(ry);
    hi = (uint32_t)__bfloat16_as_ushort(hx) | ((uint32_t)__bfloat16_as_ushort(hy) << 16);
    lo = (uint32_t)__bfloat16_as_ushort(lx) | ((uint32_t)__bfloat16_as_ushort(ly) << 16);
}

__device__ __forceinline__ void cp16(uint32_t dst, const void* src, bool p) {
    int b = p ? 16 : 0;
    asm volatile("cp.async.cg.shared.global [%0], [%1], 16, %2;" :: "r"(dst), "l"(src), "r"(b));
}

// ---------------- CSR build ----------------
// fused: zero counters + edge-dtype detection
__global__ void zero_detect_kernel(const void* __restrict__ ei) {
    int i = blockIdx.x * blockDim.x + threadIdx.x;
    if (i <= NN) g_cnt[i] = 0;
    if (i == 0) {
        const long long* p = (const long long*)ei;
        int ok = 1;
#pragma unroll
        for (int j = 0; j < 16; j++) {
            long long v = p[j];
            if (v < 0 || v >= NN) ok = 0;
        }
        g_is64 = ok;
    }
}

__device__ __forceinline__ int load_idx(const void* __restrict__ ei, int e, int which) {
    if (g_is64) return (int)((const long long*)ei)[(size_t)which * EE + e];
    return ((const int*)ei)[(size_t)which * EE + e];
}

__global__ void hist_kernel(const void* __restrict__ ei) {
    int e = blockIdx.x * blockDim.x + threadIdx.x;
    if (e >= EE) return;
    unsigned d = (unsigned)load_idx(ei, e, 1);
    if (d < NN) atomicAdd(&g_cnt[d], 1);
}

// fused: dinv + scan stage 1
__global__ void scan1_kernel() {
    __shared__ int sh[SCAN_B];
    int t = threadIdx.x, i = blockIdx.x * SCAN_B + t;
    int v = (i < NN) ? g_cnt[i] : 0;
    if (i < NN) g_dinv[i] = rsqrtf((float)(v + 1));   // +1 self loop
    sh[t] = v;
    __syncthreads();
    for (int off = 1; off < SCAN_B; off <<= 1) {
        int add = (t >= off) ? sh[t - off] : 0;
        __syncthreads();
        sh[t] += add;
        __syncthreads();
    }
    if (i < NN) g_rowptr[i] = sh[t] - v;
    if (t == SCAN_B - 1) g_bsum[blockIdx.x] = sh[SCAN_B - 1];
}

__global__ void scan2_kernel() {
    __shared__ int sh[256];
    int t = threadIdx.x;
    int v = (t < SCAN_NB) ? g_bsum[t] : 0;
    sh[t] = v;
    __syncthreads();
    for (int off = 1; off < 256; off <<= 1) {
        int add = (t >= off) ? sh[t - off] : 0;
        __syncthreads();
        sh[t] += add;
        __syncthreads();
    }
    if (t < SCAN_NB) g_boff[t] = sh[t] - v;
    if (t == 255) g_rowptr[NN] = sh[255];
}

__global__ void scan3_kernel() {
    int t = threadIdx.x, i = blockIdx.x * SCAN_B + t;
    if (i < NN) {
        int r = g_rowptr[i] + g_boff[blockIdx.x];
        g_rowptr[i] = r;
        g_fill[i]   = r;
    }
}

__global__ void fill_kernel(const void* __restrict__ ei) {
    int e = blockIdx.x * blockDim.x + threadIdx.x;
    if (e >= EE) return;
    unsigned s = (unsigned)load_idx(ei, e, 0);
    unsigned d = (unsigned)load_idx(ei, e, 1);
    if (s >= NN || d >= NN) return;
    int p = atomicAdd(&g_fill[d], 1);
    if (p < EE) {
        g_csr_src[p] = (int)s;
        g_csr_w[p]   = g_dinv[s] * g_dinv[d];
    }
}

// ---------------- conversion kernels ----------------
__global__ void conv_w_all_kernel(const float* __restrict__ w0, const float* __restrict__ w1,
                                  const float* __restrict__ w2, const float* __restrict__ w3,
                                  const float* __restrict__ w4) {
    int i = blockIdx.x * blockDim.x + threadIdx.x;
    if (i >= WTOTAL / 4) return;
    const float* src;
    int base;
    if      (i < WOFF_G1 / 4) { src = w0; base = WOFF_G0 / 4; }
    else if (i < WOFF_G2 / 4) { src = w1; base = WOFF_G1 / 4; }
    else if (i < WOFF_M0 / 4) { src = w2; base = WOFF_G2 / 4; }
    else if (i < WOFF_M1 / 4) { src = w3; base = WOFF_M0 / 4; }
    else                      { src = w4; base = WOFF_M1 / 4; }
    float4 v = ((const float4*)src)[i - base];
    uint2 hi, lo;
    split_pack(v.x, v.y, hi.x, lo.x);
    split_pack(v.z, v.w, hi.y, lo.y);
    ((uint2*)g_Wshi)[i] = hi;
    ((uint2*)g_Wslo)[i] = lo;
}

__global__ void conv_x_kernel(const float* __restrict__ x) {
    int i = blockIdx.x * blockDim.x + threadIdx.x;
    if (i >= NN * HIDD / 4) return;
    float4 v = ((const float4*)x)[i];
    uint2 hi, lo;
    split_pack(v.x, v.y, hi.x, lo.x);
    split_pack(v.z, v.w, hi.y, lo.y);
    ((uint2*)g_Ahi)[i] = hi;
    ((uint2*)g_Alo)[i] = lo;
}

// ---------------- pull aggregation + fused bias/ReLU/split ----------------
__global__ void agg_kernel(const float* __restrict__ bias) {
    const float4* __restrict__ H4 = (const float4*)g_H;
    int gw   = (blockIdx.x * blockDim.x + threadIdx.x) >> 5;
    int lane = threadIdx.x & 31;
    if (gw >= NN) return;
    float sw = g_dinv[gw];
    sw *= sw;
    float4 a = H4[(size_t)gw * 32 + lane];
    a.x *= sw; a.y *= sw; a.z *= sw; a.w *= sw;
    int e = g_rowptr[gw], end = g_rowptr[gw + 1];

    for (; e + 8 <= end; e += 8) {
        int   s0 = g_csr_src[e + 0], s1 = g_csr_src[e + 1];
        int   s2 = g_csr_src[e + 2], s3 = g_csr_src[e + 3];
        int   s4 = g_csr_src[e + 4], s5 = g_csr_src[e + 5];
        int   s6 = g_csr_src[e + 6], s7 = g_csr_src[e + 7];
        float w0 = g_csr_w[e + 0], w1 = g_csr_w[e + 1];
        float w2 = g_csr_w[e + 2], w3 = g_csr_w[e + 3];
        float w4 = g_csr_w[e + 4], w5 = g_csr_w[e + 5];
        float w6 = g_csr_w[e + 6], w7 = g_csr_w[e + 7];
        float4 h0 = H4[(size_t)s0 * 32 + lane];
        float4 h1 = H4[(size_t)s1 * 32 + lane];
        float4 h2 = H4[(size_t)s2 * 32 + lane];
        float4 h3 = H4[(size_t)s3 * 32 + lane];
        float4 h4 = H4[(size_t)s4 * 32 + lane];
        float4 h5 = H4[(size_t)s5 * 32 + lane];
        float4 h6 = H4[(size_t)s6 * 32 + lane];
        float4 h7 = H4[(size_t)s7 * 32 + lane];
        a.x = fmaf(h0.x, w0, a.x); a.y = fmaf(h0.y, w0, a.y); a.z = fmaf(h0.z, w0, a.z); a.w = fmaf(h0.w, w0, a.w);
        a.x = fmaf(h1.x, w1, a.x); a.y = fmaf(h1.y, w1, a.y); a.z = fmaf(h1.z, w1, a.z); a.w = fmaf(h1.w, w1, a.w);
        a.x = fmaf(h2.x, w2, a.x); a.y = fmaf(h2.y, w2, a.y); a.z = fmaf(h2.z, w2, a.z); a.w = fmaf(h2.w, w2, a.w);
        a.x = fmaf(h3.x, w3, a.x); a.y = fmaf(h3.y, w3, a.y); a.z = fmaf(h3.z, w3, a.z); a.w = fmaf(h3.w, w3, a.w);
        a.x = fmaf(h4.x, w4, a.x); a.y = fmaf(h4.y, w4, a.y); a.z = fmaf(h4.z, w4, a.z); a.w = fmaf(h4.w, w4, a.w);
        a.x = fmaf(h5.x, w5, a.x); a.y = fmaf(h5.y, w5, a.y); a.z = fmaf(h5.z, w5, a.z); a.w = fmaf(h5.w, w5, a.w);
        a.x = fmaf(h6.x, w6, a.x); a.y = fmaf(h6.y, w6, a.y); a.z = fmaf(h6.z, w6, a.z); a.w = fmaf(h6.w, w6, a.w);
        a.x = fmaf(h7.x, w7, a.x); a.y = fmaf(h7.y, w7, a.y); a.z = fmaf(h7.z, w7, a.z); a.w = fmaf(h7.w, w7, a.w);
    }
    for (; e < end; e++) {
        int   s  = g_csr_src[e];
        float wv = g_csr_w[e];
        float4 h = H4[(size_t)s * 32 + lane];
        a.x = fmaf(h.x, wv, a.x);
        a.y = fmaf(h.y, wv, a.y);
        a.z = fmaf(h.z, wv, a.z);
        a.w = fmaf(h.w, wv, a.w);
    }
    const float4 b4 = ((const float4*)bias)[lane];
    a.x = fmaxf(a.x + b4.x, 0.f);
    a.y = fmaxf(a.y + b4.y, 0.f);
    a.z = fmaxf(a.z + b4.z, 0.f);
    a.w = fmaxf(a.w + b4.w, 0.f);
    uint2 hi, lo;
    split_pack(a.x, a.y, hi.x, lo.x);
    split_pack(a.z, a.w, hi.y, lo.y);
    ((uint2*)g_Ahi)[(size_t)gw * 32 + lane] = hi;
    ((uint2*)g_Alo)[(size_t)gw * 32 + lane] = lo;
}

// ================= mma.sync GEMM: pre-split bf16, 3-stage cp.async, 1 sync/k-tile =================
__device__ __forceinline__ void ldsm4(uint32_t& r0, uint32_t& r1, uint32_t& r2, uint32_t& r3, uint32_t addr) {
    asm volatile("ldmatrix.sync.aligned.m8n8.x4.shared.b16 {%0,%1,%2,%3}, [%4];"
                 : "=r"(r0), "=r"(r1), "=r"(r2), "=r"(r3) : "r"(addr));
}
__device__ __forceinline__ void ldsm4t(uint32_t& r0, uint32_t& r1, uint32_t& r2, uint32_t& r3, uint32_t addr) {
    asm volatile("ldmatrix.sync.aligned.m8n8.x4.trans.shared.b16 {%0,%1,%2,%3}, [%4];"
                 : "=r"(r0), "=r"(r1), "=r"(r2), "=r"(r3) : "r"(addr));
}
__device__ __forceinline__ void mma16816(float* c, const uint32_t* a, uint32_t b0, uint32_t b1) {
    asm("mma.sync.aligned.m16n8k16.row.col.f32.bf16.bf16.f32 "
        "{%0,%1,%2,%3},{%4,%5,%6,%7},{%8,%9},{%0,%1,%2,%3};"
        : "+f"(c[0]), "+f"(c[1]), "+f"(c[2]), "+f"(c[3])
        : "r"(a[0]), "r"(a[1]), "r"(a[2]), "r"(a[3]), "r"(b0), "r"(b1));
}

#define ASTRIDE 40     // bf16; 80B rows, LDSM conflict-free
#define WSTRIDE 136    // bf16; 272B rows
#define BM 64

#define ASZ (BM * ASTRIDE)                 // 2560 elems
#define WSZ (32 * WSTRIDE)                 // 4352 elems
#define SSE (2 * ASZ + 2 * WSZ)            // 13824 elems / stage
#define NSTAGE 3
#define SMEM_BYTES (NSTAGE * SSE * 2)      // 82944 B

// BM=64, BN=128, BK=32; 8 warps (2m x 4n, 32x32/warp); 3-stage pipeline, one barrier per k-tile.
// ASEL: 0 = g_A (K=HIDD), 1 = g_B (K=MLP0).
// OUT:  0 = fp32 -> g_H, 1 = bias+relu+split -> g_B, 2 = bias+relu fp32 -> Cout.
template <int K, int ASEL, int OUT>
__global__ void __launch_bounds__(256, 2)
gemm_tc(const float* __restrict__ bias, float* __restrict__ Cout, int M, int Nout, int woff) {
    constexpr int NT = 4;
    constexpr int NP = 2;
    constexpr int NK = K / 32;

    const __nv_bfloat16* Ahi = (ASEL == 0) ? g_Ahi : g_Bhi;
    const __nv_bfloat16* Alo = (ASEL == 0) ? g_Alo : g_Blo;
    const __nv_bfloat16* Whi = g_Wshi + woff;
    const __nv_bfloat16* Wlo = g_Wslo + woff;

    extern __shared__ __nv_bfloat16 smem[];

    const int tid  = threadIdx.x;
    const int lane = tid & 31;
    const int wid  = tid >> 5;
    const int wm   = wid & 1;
    const int wn   = wid >> 1;
    const int row0 = blockIdx.x * BM;
    const int col0 = blockIdx.y * 128;

    const uint32_t sb = (uint32_t)__cvta_generic_to_shared(smem);

    float acc[2][NT][4];
#pragma unroll
    for (int i = 0; i < 2; i++)
#pragma unroll
        for (int j = 0; j < NT; j++)
#pragma unroll
            for (int q = 0; q < 4; q++) acc[i][j][q] = 0.f;

    const int lrow  = (lane & 7) + ((lane >> 3) & 1) * 8;
    const int lhalf = lane >> 4;

    auto issue_tile = [&](int k0, int st) {
        uint32_t stb = sb + (uint32_t)(st * SSE) * 2;
        {
            int idx = tid;                 // 256 quads = 64 rows x 4 chunks
            int r  = idx >> 2;
            int kq = idx & 3;
            int grow = row0 + r;
            bool p = grow < M;
            size_t goff = (size_t)(p ? grow : 0) * K + k0 + kq * 8;
            uint32_t d = stb + (uint32_t)(r * ASTRIDE + kq * 8) * 2;
            cp16(d, Ahi + goff, p);
            cp16(d + (uint32_t)ASZ * 2, Alo + goff, p);
        }
#pragma unroll
        for (int h = 0; h < 2; h++) {
            int idx = tid + h * 256;
            int r  = idx >> 4;
            int cq = idx & 15;
            size_t goff = (size_t)(k0 + r) * Nout + col0 + cq * 8;
            uint32_t d = stb + (uint32_t)(2 * ASZ + r * WSTRIDE + cq * 8) * 2;
            cp16(d, Whi + goff, true);
            cp16(d + (uint32_t)WSZ * 2, Wlo + goff, true);
        }
        asm volatile("cp.async.commit_group;");
    };

    issue_tile(0, 0);
    if (NK > 1) issue_tile(32, 1);

    for (int i = 0; i < NK; i++) {
        // tile i must be complete; up to 1 newer group may remain in flight
        if (i < NK - 1) asm volatile("cp.async.wait_group 1;");
        else            asm volatile("cp.async.wait_group 0;");
        __syncthreads();
        // safe to refill stage (i+2)%3 == stage of tile i-1: the barrier above
        // proves every warp finished MMA(i-1) (wait/sync follow it in program order)
        if (i + 2 < NK) issue_tile((i + 2) * 32, (i + 2) % NSTAGE);

        const uint32_t stb = sb + (uint32_t)((i % NSTAGE) * SSE) * 2;
#pragma unroll
        for (int ks = 0; ks < 2; ks++) {
            uint32_t ah[2][4], al[2][4];
#pragma unroll
            for (int mt = 0; mt < 2; mt++) {
                int arow = wm * 32 + mt * 16 + lrow;
                int acol = ks * 16 + lhalf * 8;
                uint32_t base = stb + (uint32_t)(arow * ASTRIDE + acol) * 2;
                ldsm4(ah[mt][0], ah[mt][1], ah[mt][2], ah[mt][3], base);
                ldsm4(al[mt][0], al[mt][1], al[mt][2], al[mt][3], base + (uint32_t)ASZ * 2);
            }
#pragma unroll
            for (int np = 0; np < NP; np++) {
                int wrow = ks * 16 + lrow;
                int wcol = wn * 32 + np * 16 + lhalf * 8;
                uint32_t base = stb + (uint32_t)(2 * ASZ + wrow * WSTRIDE + wcol) * 2;
                uint32_t bh[4], bl[4];
                ldsm4t(bh[0], bh[1], bh[2], bh[3], base);
                ldsm4t(bl[0], bl[1], bl[2], bl[3], base + (uint32_t)WSZ * 2);
#pragma unroll
                for (int mt = 0; mt < 2; mt++) {
#pragma unroll
                    for (int nl = 0; nl < 2; nl++) {
                        float* c = acc[mt][np * 2 + nl];
                        mma16816(c, ah[mt], bh[nl * 2], bh[nl * 2 + 1]);
                        mma16816(c, ah[mt], bl[nl * 2], bl[nl * 2 + 1]);
                        mma16816(c, al[mt], bh[nl * 2], bh[nl * 2 + 1]);
                    }
                }
            }
        }
    }

    const int gi = lane >> 2;
    const int qi = lane & 3;
#pragma unroll
    for (int mt = 0; mt < 2; mt++) {
#pragma unroll
        for (int nt = 0; nt < NT; nt++) {
            float* c = acc[mt][nt];
            int col  = col0 + wn * 32 + nt * 8 + qi * 2;
            int r0r  = row0 + wm * 32 + mt * 16 + gi;
            float2 v0 = make_float2(c[0], c[1]);
            float2 v1 = make_float2(c[2], c[3]);
            if (OUT != 0) {
                float b0 = bias[col], b1 = bias[col + 1];
                v0.x = fmaxf(v0.x + b0, 0.f); v0.y = fmaxf(v0.y + b1, 0.f);
                v1.x = fmaxf(v1.x + b0, 0.f); v1.y = fmaxf(v1.y + b1, 0.f);
            }
            if (OUT == 0) {
                if (r0r < M)     *(float2*)(g_H + (size_t)r0r * Nout + col)       = v0;
                if (r0r + 8 < M) *(float2*)(g_H + (size_t)(r0r + 8) * Nout + col) = v1;
            } else if (OUT == 1) {
                uint32_t hi0, lo0, hi1, lo1;
                split_pack(v0.x, v0.y, hi0, lo0);
                split_pack(v1.x, v1.y, hi1, lo1);
                if (r0r < M) {
                    *(uint32_t*)(g_Bhi + (size_t)r0r * Nout + col) = hi0;
                    *(uint32_t*)(g_Blo + (size_t)r0r * Nout + col) = lo0;
                }
                if (r0r + 8 < M) {
                    *(uint32_t*)(g_Bhi + (size_t)(r0r + 8) * Nout + col) = hi1;
                    *(uint32_t*)(g_Blo + (size_t)(r0r + 8) * Nout + col) = lo1;
                }
            } else {
                if (r0r < M)     *(float2*)(Cout + (size_t)r0r * Nout + col)       = v0;
                if (r0r + 8 < M) *(float2*)(Cout + (size_t)(r0r + 8) * Nout + col) = v1;
            }
        }
    }
}

// ---------------- launch ----------------
extern "C" void kernel_launch(void* const* d_in, const int* in_sizes, int n_in,
                              void* d_out, int out_size) {
    const float* x   = (const float*)d_in[0];
    const void*  ei  = d_in[1];
    const float* Wg0 = (const float*)d_in[2];
    const float* bg0 = (const float*)d_in[3];
    const float* Wg1 = (const float*)d_in[4];
    const float* bg1 = (const float*)d_in[5];
    const float* Wg2 = (const float*)d_in[6];
    const float* bg2 = (const float*)d_in[7];
    const float* Wm0 = (const float*)d_in[8];
    const float* bm0 = (const float*)d_in[9];
    const float* Wm1 = (const float*)d_in[10];
    const float* bm1 = (const float*)d_in[11];
    float*       out = (float*)d_out;

    cudaFuncSetAttribute(gemm_tc<128, 0, 0>, cudaFuncAttributeMaxDynamicSharedMemorySize, SMEM_BYTES);
    cudaFuncSetAttribute(gemm_tc<128, 0, 1>, cudaFuncAttributeMaxDynamicSharedMemorySize, SMEM_BYTES);
    cudaFuncSetAttribute(gemm_tc<512, 1, 2>, cudaFuncAttributeMaxDynamicSharedMemorySize, SMEM_BYTES);

    dim3 blk(256);
    const int MB64 = (NN + 63) / 64;      // 782
    dim3 gG(MB64, 1);                     // GCN: N=128
    dim3 gM0(MB64, 4);                    // MLP0: N=512
    dim3 gM1(MB64, 2);                    // MLP1: N=256
    int aggBlocks = (NN * 32 + 255) / 256;

    // ---- keep gemm_tc at launch position 4 for the ncu window ----
    conv_x_kernel<<<(NN * HIDD / 4 + 255) / 256, 256>>>(x);                          // 1
    conv_w_all_kernel<<<(WTOTAL / 4 + 255) / 256, 256>>>(Wg0, Wg1, Wg2, Wm0, Wm1);   // 2
    zero_detect_kernel<<<(NN + 256) / 256, 256>>>(ei);                               // 3
    gemm_tc<128, 0, 0><<<gG, blk, SMEM_BYTES>>>(nullptr, nullptr, NN, HIDD, WOFF_G0); // 4 <- profiled
    // ---- CSR build ----
    hist_kernel<<<(EE + 255) / 256, 256>>>(ei);
    scan1_kernel<<<SCAN_NB, SCAN_B>>>();
    scan2_kernel<<<1, 256>>>();
    scan3_kernel<<<SCAN_NB, SCAN_B>>>();
    fill_kernel<<<(EE + 255) / 256, 256>>>(ei);

    // ---- GCN layers ----
    agg_kernel<<<aggBlocks, 256>>>(bg0);
    gemm_tc<128, 0, 0><<<gG, blk, SMEM_BYTES>>>(nullptr, nullptr, NN, HIDD, WOFF_G1);
    agg_kernel<<<aggBlocks, 256>>>(bg1);
    gemm_tc<128, 0, 0><<<gG, blk, SMEM_BYTES>>>(nullptr, nullptr, NN, HIDD, WOFF_G2);
    agg_kernel<<<aggBlocks, 256>>>(bg2);
    // ---- MLP head ----
    gemm_tc<128, 0, 1><<<gM0, blk, SMEM_BYTES>>>(bm0, nullptr, NN, MLP0, WOFF_M0);
    gemm_tc<512, 1, 2><<<gM1, blk, SMEM_BYTES>>>(bm1, out, NN, MLP1, WOFF_M1);
}

// round 16
// speedup vs baseline: 1.0286x; 1.0286x over previous
#include <cuda_runtime.h>
#include <cuda_bf16.h>
#include <cstdint>

#define NN   50000
#define EE   800000
#define HIDD 128
#define MLP0 512
#define MLP1 256

// weight arena offsets (elements)
#define WOFF_G0 0
#define WOFF_G1 16384
#define WOFF_G2 32768
#define WOFF_M0 49152
#define WOFF_M1 114688
#define WTOTAL  245760

// ---------------- scratch (device globals; device-code-only references) ----------------
__device__ float         g_H[(size_t)NN * HIDD];
__device__ __nv_bfloat16 g_Ahi[(size_t)NN * HIDD];
__device__ __nv_bfloat16 g_Alo[(size_t)NN * HIDD];
__device__ __nv_bfloat16 g_Bhi[(size_t)NN * MLP0];
__device__ __nv_bfloat16 g_Blo[(size_t)NN * MLP0];
__device__ __nv_bfloat16 g_Wshi[WTOTAL];
__device__ __nv_bfloat16 g_Wslo[WTOTAL];
__device__ int   g_cnt[NN + 1];
__device__ int   g_rowptr[NN + 1];
__device__ int   g_fill[NN];
__device__ float g_dinv[NN];
__device__ int   g_csr_src[EE];
__device__ float g_csr_w[EE];
__device__ int   g_is64;
__device__ int   g_bsum[256];
__device__ int   g_boff[256];

#define SCAN_B 256
#define SCAN_NB ((NN + SCAN_B - 1) / SCAN_B)   // 196

// ---------------- helpers ----------------
__device__ __forceinline__ void split_pack(float x, float y, uint32_t& hi, uint32_t& lo) {
    __nv_bfloat16 hx = __float2bfloat16_rn(x);
    __nv_bfloat16 hy = __float2bfloat16_rn(y);
    float rx = x - __bfloat162float(hx);
    float ry = y - __bfloat162float(hy);
    __nv_bfloat16 lx = __float2bfloat16_rn(rx);
    __nv_bfloat16 ly = __float2bfloat16_rn(ry);
    hi = (uint32_t)__bfloat16_as_ushort(hx) | ((uint32_t)__bfloat16_as_ushort(hy) << 16);
    lo = (uint32_t)__bfloat16_as_ushort(lx) | ((uint32_t)__bfloat16_as_ushort(ly) << 16);
}

__device__ __forceinline__ void cp16(uint32_t dst, const void* src, bool p) {
    int b = p ? 16 : 0;
    asm volatile("cp.async.cg.shared.global [%0], [%1], 16, %2;" :: "r"(dst), "l"(src), "r"(b));
}
// L1-cached variant: W tiles are shared by co-resident CTAs (same blockIdx.y)
// and re-read every k-tile -> keep them in L1.
__device__ __forceinline__ void cp16ca(uint32_t dst, const void* src) {
    asm volatile("cp.async.ca.shared.global [%0], [%1], 16;" :: "r"(dst), "l"(src));
}

// ---------------- CSR build ----------------
__global__ void zero_detect_kernel(const void* __restrict__ ei) {
    int i = blockIdx.x * blockDim.x + threadIdx.x;
    if (i <= NN) g_cnt[i] = 0;
    if (i == 0) {
        const long long* p = (const long long*)ei;
        int ok = 1;
#pragma unroll
        for (int j = 0; j < 16; j++) {
            long long v = p[j];
            if (v < 0 || v >= NN) ok = 0;
        }
        g_is64 = ok;
    }
}

__device__ __forceinline__ int load_idx(const void* __restrict__ ei, int e, int which) {
    if (g_is64) return (int)((const long long*)ei)[(size_t)which * EE + e];
    return ((const int*)ei)[(size_t)which * EE + e];
}

__global__ void hist_kernel(const void* __restrict__ ei) {
    int e = blockIdx.x * blockDim.x + threadIdx.x;
    if (e >= EE) return;
    unsigned d = (unsigned)load_idx(ei, e, 1);
    if (d < NN) atomicAdd(&g_cnt[d], 1);
}

__global__ void scan1_kernel() {
    __shared__ int sh[SCAN_B];
    int t = threadIdx.x, i = blockIdx.x * SCAN_B + t;
    int v = (i < NN) ? g_cnt[i] : 0;
    if (i < NN) g_dinv[i] = rsqrtf((float)(v + 1));   // +1 self loop
    sh[t] = v;
    __syncthreads();
    for (int off = 1; off < SCAN_B; off <<= 1) {
        int add = (t >= off) ? sh[t - off] : 0;
        __syncthreads();
        sh[t] += add;
        __syncthreads();
    }
    if (i < NN) g_rowptr[i] = sh[t] - v;
    if (t == SCAN_B - 1) g_bsum[blockIdx.x] = sh[SCAN_B - 1];
}

__global__ void scan2_kernel() {
    __shared__ int sh[256];
    int t = threadIdx.x;
    int v = (t < SCAN_NB) ? g_bsum[t] : 0;
    sh[t] = v;
    __syncthreads();
    for (int off = 1; off < 256; off <<= 1) {
        int add = (t >= off) ? sh[t - off] : 0;
        __syncthreads();
        sh[t] += add;
        __syncthreads();
    }
    if (t < SCAN_NB) g_boff[t] = sh[t] - v;
    if (t == 255) g_rowptr[NN] = sh[255];
}

__global__ void scan3_kernel() {
    int t = threadIdx.x, i = blockIdx.x * SCAN_B + t;
    if (i < NN) {
        int r = g_rowptr[i] + g_boff[blockIdx.x];
        g_rowptr[i] = r;
        g_fill[i]   = r;
    }
}

__global__ void fill_kernel(const void* __restrict__ ei) {
    int e = blockIdx.x * blockDim.x + threadIdx.x;
    if (e >= EE) return;
    unsigned s = (unsigned)load_idx(ei, e, 0);
    unsigned d = (unsigned)load_idx(ei, e, 1);
    if (s >= NN || d >= NN) return;
    int p = atomicAdd(&g_fill[d], 1);
    if (p < EE) {
        g_csr_src[p] = (int)s;
        g_csr_w[p]   = g_dinv[s] * g_dinv[d];
    }
}

// ---------------- conversion kernels ----------------
__global__ void conv_w_all_kernel(const float* __restrict__ w0, const float* __restrict__ w1,
                                  const float* __restrict__ w2, const float* __restrict__ w3,
                                  const float* __restrict__ w4) {
    int i = blockIdx.x * blockDim.x + threadIdx.x;
    if (i >= WTOTAL / 4) return;
    const float* src;
    int base;
    if      (i < WOFF_G1 / 4) { src = w0; base = WOFF_G0 / 4; }
    else if (i < WOFF_G2 / 4) { src = w1; base = WOFF_G1 / 4; }
    else if (i < WOFF_M0 / 4) { src = w2; base = WOFF_G2 / 4; }
    else if (i < WOFF_M1 / 4) { src = w3; base = WOFF_M0 / 4; }
    else                      { src = w4; base = WOFF_M1 / 4; }
    float4 v = ((const float4*)src)[i - base];
    uint2 hi, lo;
    split_pack(v.x, v.y, hi.x, lo.x);
    split_pack(v.z, v.w, hi.y, lo.y);
    ((uint2*)g_Wshi)[i] = hi;
    ((uint2*)g_Wslo)[i] = lo;
}

__global__ void conv_x_kernel(const float* __restrict__ x) {
    int i = blockIdx.x * blockDim.x + threadIdx.x;
    if (i >= NN * HIDD / 4) return;
    float4 v = ((const float4*)x)[i];
    uint2 hi, lo;
    split_pack(v.x, v.y, hi.x, lo.x);
    split_pack(v.z, v.w, hi.y, lo.y);
    ((uint2*)g_Ahi)[i] = hi;
    ((uint2*)g_Alo)[i] = lo;
}

// ---------------- pull aggregation + fused bias/ReLU/split ----------------
__global__ void agg_kernel(const float* __restrict__ bias) {
    const float4* __restrict__ H4 = (const float4*)g_H;
    int gw   = (blockIdx.x * blockDim.x + threadIdx.x) >> 5;
    int lane = threadIdx.x & 31;
    if (gw >= NN) return;
    float sw = g_dinv[gw];
    sw *= sw;
    float4 a = H4[(size_t)gw * 32 + lane];
    a.x *= sw; a.y *= sw; a.z *= sw; a.w *= sw;
    int e = g_rowptr[gw], end = g_rowptr[gw + 1];

    for (; e + 8 <= end; e += 8) {
        int   s0 = g_csr_src[e + 0], s1 = g_csr_src[e + 1];
        int   s2 = g_csr_src[e + 2], s3 = g_csr_src[e + 3];
        int   s4 = g_csr_src[e + 4], s5 = g_csr_src[e + 5];
        int   s6 = g_csr_src[e + 6], s7 = g_csr_src[e + 7];
        float w0 = g_csr_w[e + 0], w1 = g_csr_w[e + 1];
        float w2 = g_csr_w[e + 2], w3 = g_csr_w[e + 3];
        float w4 = g_csr_w[e + 4], w5 = g_csr_w[e + 5];
        float w6 = g_csr_w[e + 6], w7 = g_csr_w[e + 7];
        float4 h0 = H4[(size_t)s0 * 32 + lane];
        float4 h1 = H4[(size_t)s1 * 32 + lane];
        float4 h2 = H4[(size_t)s2 * 32 + lane];
        float4 h3 = H4[(size_t)s3 * 32 + lane];
        float4 h4 = H4[(size_t)s4 * 32 + lane];
        float4 h5 = H4[(size_t)s5 * 32 + lane];
        float4 h6 = H4[(size_t)s6 * 32 + lane];
        float4 h7 = H4[(size_t)s7 * 32 + lane];
        a.x = fmaf(h0.x, w0, a.x); a.y = fmaf(h0.y, w0, a.y); a.z = fmaf(h0.z, w0, a.z); a.w = fmaf(h0.w, w0, a.w);
        a.x = fmaf(h1.x, w1, a.x); a.y = fmaf(h1.y, w1, a.y); a.z = fmaf(h1.z, w1, a.z); a.w = fmaf(h1.w, w1, a.w);
        a.x = fmaf(h2.x, w2, a.x); a.y = fmaf(h2.y, w2, a.y); a.z = fmaf(h2.z, w2, a.z); a.w = fmaf(h2.w, w2, a.w);
        a.x = fmaf(h3.x, w3, a.x); a.y = fmaf(h3.y, w3, a.y); a.z = fmaf(h3.z, w3, a.z); a.w = fmaf(h3.w, w3, a.w);
        a.x = fmaf(h4.x, w4, a.x); a.y = fmaf(h4.y, w4, a.y); a.z = fmaf(h4.z, w4, a.z); a.w = fmaf(h4.w, w4, a.w);
        a.x = fmaf(h5.x, w5, a.x); a.y = fmaf(h5.y, w5, a.y); a.z = fmaf(h5.z, w5, a.z); a.w = fmaf(h5.w, w5, a.w);
        a.x = fmaf(h6.x, w6, a.x); a.y = fmaf(h6.y, w6, a.y); a.z = fmaf(h6.z, w6, a.z); a.w = fmaf(h6.w, w6, a.w);
        a.x = fmaf(h7.x, w7, a.x); a.y = fmaf(h7.y, w7, a.y); a.z = fmaf(h7.z, w7, a.z); a.w = fmaf(h7.w, w7, a.w);
    }
    for (; e < end; e++) {
        int   s  = g_csr_src[e];
        float wv = g_csr_w[e];
        float4 h = H4[(size_t)s * 32 + lane];
        a.x = fmaf(h.x, wv, a.x);
        a.y = fmaf(h.y, wv, a.y);
        a.z = fmaf(h.z, wv, a.z);
        a.w = fmaf(h.w, wv, a.w);
    }
    const float4 b4 = ((const float4*)bias)[lane];
    a.x = fmaxf(a.x + b4.x, 0.f);
    a.y = fmaxf(a.y + b4.y, 0.f);
    a.z = fmaxf(a.z + b4.z, 0.f);
    a.w = fmaxf(a.w + b4.w, 0.f);
    uint2 hi, lo;
    split_pack(a.x, a.y, hi.x, lo.x);
    split_pack(a.z, a.w, hi.y, lo.y);
    ((uint2*)g_Ahi)[(size_t)gw * 32 + lane] = hi;
    ((uint2*)g_Alo)[(size_t)gw * 32 + lane] = lo;
}

// ================= mma.sync GEMM: pre-split bf16, 3-stage cp.async, W via L1 =================
__device__ __forceinline__ void ldsm4(uint32_t& r0, uint32_t& r1, uint32_t& r2, uint32_t& r3, uint32_t addr) {
    asm volatile("ldmatrix.sync.aligned.m8n8.x4.shared.b16 {%0,%1,%2,%3}, [%4];"
                 : "=r"(r0), "=r"(r1), "=r"(r2), "=r"(r3) : "r"(addr));
}
__device__ __forceinline__ void ldsm4t(uint32_t& r0, uint32_t& r1, uint32_t& r2, uint32_t& r3, uint32_t addr) {
    asm volatile("ldmatrix.sync.aligned.m8n8.x4.trans.shared.b16 {%0,%1,%2,%3}, [%4];"
                 : "=r"(r0), "=r"(r1), "=r"(r2), "=r"(r3) : "r"(addr));
}
__device__ __forceinline__ void mma16816(float* c, const uint32_t* a, uint32_t b0, uint32_t b1) {
    asm("mma.sync.aligned.m16n8k16.row.col.f32.bf16.bf16.f32 "
        "{%0,%1,%2,%3},{%4,%5,%6,%7},{%8,%9},{%0,%1,%2,%3};"
        : "+f"(c[0]), "+f"(c[1]), "+f"(c[2]), "+f"(c[3])
        : "r"(a[0]), "r"(a[1]), "r"(a[2]), "r"(a[3]), "r"(b0), "r"(b1));
}

#define ASTRIDE 40     // bf16; 80B rows, LDSM conflict-free
#define WSTRIDE 136    // bf16; 272B rows
#define BM 64

#define ASZ (BM * ASTRIDE)                 // 2560 elems
#define WSZ (32 * WSTRIDE)                 // 4352 elems
#define SSE (2 * ASZ + 2 * WSZ)            // 13824 elems / stage
#define NSTAGE 3
#define SMEM_BYTES (NSTAGE * SSE * 2)      // 82944 B

// BM=64, BN=128, BK=32; 8 warps (2m x 4n, 32x32/warp); 3-stage pipeline, 1 barrier/k-tile.
// ASEL: 0 = g_A (K=HIDD), 1 = g_B (K=MLP0).
// OUT:  0 = fp32 -> g_H, 1 = bias+relu+split -> g_B, 2 = bias+relu fp32 -> Cout.
template <int K, int ASEL, int OUT>
__global__ void __launch_bounds__(256, 2)
gemm_tc(const float* __restrict__ bias, float* __restrict__ Cout, int M, int Nout, int woff) {
    constexpr int NT = 4;
    constexpr int NK = K / 32;

    const __nv_bfloat16* Ahi = (ASEL == 0) ? g_Ahi : g_Bhi;
    const __nv_bfloat16* Alo = (ASEL == 0) ? g_Alo : g_Blo;
    const __nv_bfloat16* Whi = g_Wshi + woff;
    const __nv_bfloat16* Wlo = g_Wslo + woff;

    extern __shared__ __nv_bfloat16 smem[];

    const int tid  = threadIdx.x;
    const int lane = tid & 31;
    const int wid  = tid >> 5;
    const int wm   = wid & 1;
    const int wn   = wid >> 1;
    const int row0 = blockIdx.x * BM;
    const int col0 = blockIdx.y * 128;

    const uint32_t sb = (uint32_t)__cvta_generic_to_shared(smem);

    float acc[2][NT][4];
#pragma unroll
    for (int i = 0; i < 2; i++)
#pragma unroll
        for (int j = 0; j < NT; j++)
#pragma unroll
            for (int q = 0; q < 4; q++) acc[i][j][q] = 0.f;

    const int lrow  = (lane & 7) + ((lane >> 3) & 1) * 8;
    const int lhalf = lane >> 4;

    auto issue_tile = [&](int k0, int st) {
        uint32_t stb = sb + (uint32_t)(st * SSE) * 2;
        {
            int idx = tid;                 // 256 quads = 64 rows x 4 chunks
            int r  = idx >> 2;
            int kq = idx & 3;
            int grow = row0 + r;
            bool p = grow < M;
            size_t goff = (size_t)(p ? grow : 0) * K + k0 + kq * 8;
            uint32_t d = stb + (uint32_t)(r * ASTRIDE + kq * 8) * 2;
            cp16(d, Ahi + goff, p);
            cp16(d + (uint32_t)ASZ * 2, Alo + goff, p);
        }
#pragma unroll
        for (int h = 0; h < 2; h++) {
            int idx = tid + h * 256;
            int r  = idx >> 4;
            int cq = idx & 15;
            size_t goff = (size_t)(k0 + r) * Nout + col0 + cq * 8;
            uint32_t d = stb + (uint32_t)(2 * ASZ + r * WSTRIDE + cq * 8) * 2;
            cp16ca(d, Whi + goff);     // W: L1-cached (shared across CTAs + k-tiles)
            cp16ca(d + (uint32_t)WSZ * 2, Wlo + goff);
        }
        asm volatile("cp.async.commit_group;");
    };

    issue_tile(0, 0);
    if (NK > 1) issue_tile(32, 1);

    for (int i = 0; i < NK; i++) {
        if (i < NK - 1) asm volatile("cp.async.wait_group 1;");
        else            asm volatile("cp.async.wait_group 0;");
        __syncthreads();
        if (i + 2 < NK) issue_tile((i + 2) * 32, (i + 2) % NSTAGE);

        const uint32_t stb = sb + (uint32_t)((i % NSTAGE) * SSE) * 2;
#pragma unroll
        for (int ks = 0; ks < 2; ks++) {
            // A fragments
            uint32_t ah[2][4], al[2][4];
#pragma unroll
            for (int mt = 0; mt < 2; mt++) {
                int arow = wm * 32 + mt * 16 + lrow;
                int acol = ks * 16 + lhalf * 8;
                uint32_t base = stb + (uint32_t)(arow * ASTRIDE + acol) * 2;
                ldsm4(ah[mt][0], ah[mt][1], ah[mt][2], ah[mt][3], base);
                ldsm4(al[mt][0], al[mt][1], al[mt][2], al[mt][3], base + (uint32_t)ASZ * 2);
            }
            // ALL B fragments hoisted (max LDSM->use distance, free MMA reordering)
            uint32_t bh[2][4], bl[2][4];
#pragma unroll
            for (int np = 0; np < 2; np++) {
                int wrow = ks * 16 + lrow;
                int wcol = wn * 32 + np * 16 + lhalf * 8;
                uint32_t base = stb + (uint32_t)(2 * ASZ + wrow * WSTRIDE + wcol) * 2;
                ldsm4t(bh[np][0], bh[np][1], bh[np][2], bh[np][3], base);
                ldsm4t(bl[np][0], bl[np][1], bl[np][2], bl[np][3], base + (uint32_t)WSZ * 2);
            }
            // term-major MMA order: 8 independent accumulators between reuses
#pragma unroll
            for (int np = 0; np < 2; np++)
#pragma unroll
                for (int mt = 0; mt < 2; mt++)
#pragma unroll
                    for (int nl = 0; nl < 2; nl++)
                        mma16816(acc[mt][np * 2 + nl], ah[mt], bh[np][nl * 2], bh[np][nl * 2 + 1]);
#pragma unroll
            for (int np = 0; np < 2; np++)
#pragma unroll
                for (int mt = 0; mt < 2; mt++)
#pragma unroll
                    for (int nl = 0; nl < 2; nl++)
                        mma16816(acc[mt][np * 2 + nl], ah[mt], bl[np][nl * 2], bl[np][nl * 2 + 1]);
#pragma unroll
            for (int np = 0; np < 2; np++)
#pragma unroll
                for (int mt = 0; mt < 2; mt++)
#pragma unroll
                    for (int nl = 0; nl < 2; nl++)
                        mma16816(acc[mt][np * 2 + nl], al[mt], bh[np][nl * 2], bh[np][nl * 2 + 1]);
        }
    }

    const int gi = lane >> 2;
    const int qi = lane & 3;
#pragma unroll
    for (int mt = 0; mt < 2; mt++) {
#pragma unroll
        for (int nt = 0; nt < NT; nt++) {
            float* c = acc[mt][nt];
            int col  = col0 + wn * 32 + nt * 8 + qi * 2;
            int r0r  = row0 + wm * 32 + mt * 16 + gi;
            float2 v0 = make_float2(c[0], c[1]);
            float2 v1 = make_float2(c[2], c[3]);
            if (OUT != 0) {
                float b0 = bias[col], b1 = bias[col + 1];
                v0.x = fmaxf(v0.x + b0, 0.f); v0.y = fmaxf(v0.y + b1, 0.f);
                v1.x = fmaxf(v1.x + b0, 0.f); v1.y = fmaxf(v1.y + b1, 0.f);
            }
            if (OUT == 0) {
                if (r0r < M)     *(float2*)(g_H + (size_t)r0r * Nout + col)       = v0;
                if (r0r + 8 < M) *(float2*)(g_H + (size_t)(r0r + 8) * Nout + col) = v1;
            } else if (OUT == 1) {
                uint32_t hi0, lo0, hi1, lo1;
                split_pack(v0.x, v0.y, hi0, lo0);
                split_pack(v1.x, v1.y, hi1, lo1);
                if (r0r < M) {
                    *(uint32_t*)(g_Bhi + (size_t)r0r * Nout + col) = hi0;
                    *(uint32_t*)(g_Blo + (size_t)r0r * Nout + col) = lo0;
                }
                if (r0r + 8 < M) {
                    *(uint32_t*)(g_Bhi + (size_t)(r0r + 8) * Nout + col) = hi1;
                    *(uint32_t*)(g_Blo + (size_t)(r0r + 8) * Nout + col) = lo1;
                }
            } else {
                if (r0r < M)     *(float2*)(Cout + (size_t)r0r * Nout + col)       = v0;
                if (r0r + 8 < M) *(float2*)(Cout + (size_t)(r0r + 8) * Nout + col) = v1;
            }
        }
    }
}

// ---------------- launch ----------------
extern "C" void kernel_launch(void* const* d_in, const int* in_sizes, int n_in,
                              void* d_out, int out_size) {
    const float* x   = (const float*)d_in[0];
    const void*  ei  = d_in[1];
    const float* Wg0 = (const float*)d_in[2];
    const float* bg0 = (const float*)d_in[3];
    const float* Wg1 = (const float*)d_in[4];
    const float* bg1 = (const float*)d_in[5];
    const float* Wg2 = (const float*)d_in[6];
    const float* bg2 = (const float*)d_in[7];
    const float* Wm0 = (const float*)d_in[8];
    const float* bm0 = (const float*)d_in[9];
    const float* Wm1 = (const float*)d_in[10];
    const float* bm1 = (const float*)d_in[11];
    float*       out = (float*)d_out;

    cudaFuncSetAttribute(gemm_tc<128, 0, 0>, cudaFuncAttributeMaxDynamicSharedMemorySize, SMEM_BYTES);
    cudaFuncSetAttribute(gemm_tc<128, 0, 1>, cudaFuncAttributeMaxDynamicSharedMemorySize, SMEM_BYTES);
    cudaFuncSetAttribute(gemm_tc<512, 1, 2>, cudaFuncAttributeMaxDynamicSharedMemorySize, SMEM_BYTES);

    dim3 blk(256);
    const int MB64 = (NN + 63) / 64;      // 782
    dim3 gG(MB64, 1);                     // GCN: N=128
    dim3 gM0(MB64, 4);                    // MLP0: N=512
    dim3 gM1(MB64, 2);                    // MLP1: N=256
    int aggBlocks = (NN * 32 + 255) / 256;

    // ---- keep gemm_tc at launch position 4 for the ncu window ----
    conv_x_kernel<<<(NN * HIDD / 4 + 255) / 256, 256>>>(x);                          // 1
    conv_w_all_kernel<<<(WTOTAL / 4 + 255) / 256, 256>>>(Wg0, Wg1, Wg2, Wm0, Wm1);   // 2
    zero_detect_kernel<<<(NN + 256) / 256, 256>>>(ei);                               // 3
    gemm_tc<128, 0, 0><<<gG, blk, SMEM_BYTES>>>(nullptr, nullptr, NN, HIDD, WOFF_G0); // 4 <- profiled
    // ---- CSR build ----
    hist_kernel<<<(EE + 255) / 256, 256>>>(ei);
    scan1_kernel<<<SCAN_NB, SCAN_B>>>();
    scan2_kernel<<<1, 256>>>();
    scan3_kernel<<<SCAN_NB, SCAN_B>>>();
    fill_kernel<<<(EE + 255) / 256, 256>>>(ei);

    // ---- GCN layers ----
    agg_kernel<<<aggBlocks, 256>>>(bg0);
    gemm_tc<128, 0, 0><<<gG, blk, SMEM_BYTES>>>(nullptr, nullptr, NN, HIDD, WOFF_G1);
    agg_kernel<<<aggBlocks, 256>>>(bg1);
    gemm_tc<128, 0, 0><<<gG, blk, SMEM_BYTES>>>(nullptr, nullptr, NN, HIDD, WOFF_G2);
    agg_kernel<<<aggBlocks, 256>>>(bg2);
    // ---- MLP head ----
    gemm_tc<128, 0, 1><<<gM0, blk, SMEM_BYTES>>>(bm0, nullptr, NN, MLP0, WOFF_M0);
    gemm_tc<512, 1, 2><<<gM1, blk, SMEM_BYTES>>>(bm1, out, NN, MLP1, WOFF_M1);
}